// round 13
// baseline (speedup 1.0000x reference)
#include <cuda_runtime.h>
#include <cuda_bf16.h>
#include <math.h>
#include <stdint.h>

#define O_DIM 1024
#define D_DIM 1024
#define E_NUM 16
#define TOPK  4
#define H_DIM 2048
#define A_DIM 64
#define NPAIR (O_DIM * TOPK)
#define FLT_MIN_NORM 1.17549435e-38f
#define MAXTILE 80

// ---------------- scratch (static device memory; no allocs) ----------------
__device__ int      g_topk_idx[NPAIR];
__device__ float    g_topk_gate[NPAIR];
__device__ float    g_importance[O_DIM];
__device__ float    g_load[O_DIM];
__device__ int      g_base[E_NUM + 1];
__device__ int      g_rows_sorted[NPAIR];
__device__ int      g_pair_of[NPAIR];
__device__ int      g_ntile;
__device__ int      g_tile_e[MAXTILE];
__device__ int      g_tile_m0[MAXTILE];
__device__ unsigned g_obs_h[O_DIM * D_DIM / 2];
__device__ unsigned g_w2p[E_NUM * (H_DIM / 2) * A_DIM];
__device__ unsigned g_h[NPAIR * H_DIM / 2];
__device__ float    g_z[4 * NPAIR * A_DIM];

#define N_OBS4 (O_DIM * D_DIM / 8)
#define N_W24  (E_NUM * (H_DIM / 2) * A_DIM / 4)
#define PREP_BLOCKS ((N_OBS4 + N_W24) / 256)           // 1536

// ---------------- helpers ----------------
__device__ __forceinline__ uint32_t smem_u32(const void* p) {
    uint32_t a;
    asm("{ .reg .u64 t; cvta.to.shared.u64 t, %1; cvt.u32.u64 %0, t; }" : "=r"(a) : "l"(p));
    return a;
}
__device__ __forceinline__ void cp_async16(uint32_t saddr, const void* gptr) {
    asm volatile("cp.async.cg.shared.global [%0], [%1], 16;" :: "r"(saddr), "l"(gptr));
}
__device__ __forceinline__ void cp_commit() {
    asm volatile("cp.async.commit_group;" ::: "memory");
}
template <int N> __device__ __forceinline__ void cp_wait() {
    asm volatile("cp.async.wait_group %0;" :: "n"(N) : "memory");
}
__device__ __forceinline__ unsigned pack_f16x2(float lo, float hi) {
    unsigned u;
    asm("cvt.rn.f16x2.f32 %0, %1, %2;" : "=r"(u) : "f"(hi), "f"(lo));
    return u;
}
__device__ __forceinline__ void ldmatrix_x4(unsigned r[4], uint32_t saddr) {
    asm volatile("ldmatrix.sync.aligned.m8n8.x4.shared.b16 {%0,%1,%2,%3}, [%4];"
                 : "=r"(r[0]), "=r"(r[1]), "=r"(r[2]), "=r"(r[3]) : "r"(saddr));
}
__device__ __forceinline__ void mma_f16(float c[4], unsigned a0, unsigned a1,
                                        unsigned a2, unsigned a3,
                                        unsigned b0, unsigned b1) {
    asm volatile(
        "mma.sync.aligned.m16n8k16.row.col.f32.f16.f16.f32 "
        "{%0,%1,%2,%3}, {%4,%5,%6,%7}, {%8,%9}, {%0,%1,%2,%3};\n"
        : "+f"(c[0]), "+f"(c[1]), "+f"(c[2]), "+f"(c[3])
        : "r"(a0), "r"(a1), "r"(a2), "r"(a3), "r"(b0), "r"(b1));
}

// ============ fused kernel 1: gate (blocks 0..1023) + prep (rest) ==========
// prep now packs only obs (small) and w2 (small); w1 is consumed fp32 by fc1.
__global__ __launch_bounds__(256) void prep_gate_kernel(const float* __restrict__ obs,
                                                        const float* __restrict__ wg,
                                                        const float* __restrict__ w2) {
    int bid = blockIdx.x;
    int tid = threadIdx.x;

    if (bid < O_DIM) {
        int o = bid;
        const float* wrow = wg + (size_t)o * D_DIM * E_NUM;
        const float* orow = obs + (size_t)o * D_DIM;

        float acc[E_NUM];
#pragma unroll
        for (int i = 0; i < E_NUM; i++) acc[i] = 0.f;
        for (int d = tid; d < D_DIM; d += 256) {
            float x = orow[d];
            const float4* p = reinterpret_cast<const float4*>(wrow + (size_t)d * E_NUM);
            float4 v0 = p[0], v1 = p[1], v2 = p[2], v3 = p[3];
            acc[0]  += x * v0.x; acc[1]  += x * v0.y; acc[2]  += x * v0.z; acc[3]  += x * v0.w;
            acc[4]  += x * v1.x; acc[5]  += x * v1.y; acc[6]  += x * v1.z; acc[7]  += x * v1.w;
            acc[8]  += x * v2.x; acc[9]  += x * v2.y; acc[10] += x * v2.z; acc[11] += x * v2.w;
            acc[12] += x * v3.x; acc[13] += x * v3.y; acc[14] += x * v3.z; acc[15] += x * v3.w;
        }
#pragma unroll
        for (int i = 0; i < E_NUM; i++) {
#pragma unroll
            for (int off = 16; off; off >>= 1)
                acc[i] += __shfl_xor_sync(0xffffffffu, acc[i], off);
        }
        __shared__ float s[8][E_NUM];
        int warp = tid >> 5, lane = tid & 31;
        if (lane == 0) {
#pragma unroll
            for (int i = 0; i < E_NUM; i++) s[warp][i] = acc[i];
        }
        __syncthreads();
        if (tid == 0) {
            float logit[E_NUM];
            for (int e = 0; e < E_NUM; e++) {
                float t = 0.f;
                for (int w = 0; w < 8; w++) t += s[w][e];
                logit[e] = t;
            }
            bool taken[E_NUM];
            for (int e = 0; e < E_NUM; e++) taken[e] = false;
            int idx[TOPK]; float val[TOPK];
            for (int k = 0; k < TOPK; k++) {
                float best = -3.4e38f; int bi = 0;
                for (int e = 0; e < E_NUM; e++)
                    if (!taken[e] && logit[e] > best) { best = logit[e]; bi = e; }
                taken[bi] = true; idx[k] = bi; val[k] = best;
            }
            float m = val[0];
            float ex[TOPK]; float se = 0.f;
            for (int k = 0; k < TOPK; k++) { ex[k] = expf(val[k] - m); se += ex[k]; }
            float gates[E_NUM];
            for (int e = 0; e < E_NUM; e++) gates[e] = 0.f;
            for (int k = 0; k < TOPK; k++) gates[idx[k]] = ex[k] / se;
            float imp = 0.f; int ldc = 0;
            for (int e = 0; e < E_NUM; e++) { imp += gates[e]; ldc += (gates[e] > 0.f); }
            for (int k = 0; k < TOPK; k++) {
                g_topk_idx[o * TOPK + k]  = idx[k];
                g_topk_gate[o * TOPK + k] = gates[idx[k]];
            }
            g_importance[o] = imp;
            g_load[o] = (float)ldc;
        }
        return;
    }

    int idx = (bid - O_DIM) * 256 + tid;
    if (idx < N_OBS4) {
        const float4* p = reinterpret_cast<const float4*>(obs) + idx * 2;
        float4 f0 = p[0], f1 = p[1];
        uint4 u;
        u.x = pack_f16x2(f0.x, f0.y);
        u.y = pack_f16x2(f0.z, f0.w);
        u.z = pack_f16x2(f1.x, f1.y);
        u.w = pack_f16x2(f1.z, f1.w);
        reinterpret_cast<uint4*>(g_obs_h)[idx] = u;
    } else if (idx < N_OBS4 + N_W24) {
        int t = idx - N_OBS4;
        int e  = t >> 14;
        int r  = t & 16383;
        int kp = r >> 4;
        int n4 = (r & 15) * 4;
        const float* p = w2 + ((size_t)e << 17) + (kp << 7) + n4;
        float4 f0 = *reinterpret_cast<const float4*>(p);
        float4 f1 = *reinterpret_cast<const float4*>(p + 64);
        uint4 u;
        u.x = pack_f16x2(f0.x, f1.x);
        u.y = pack_f16x2(f0.y, f1.y);
        u.z = pack_f16x2(f0.z, f1.z);
        u.w = pack_f16x2(f0.w, f1.w);
        *reinterpret_cast<uint4*>(g_w2p + ((size_t)e << 16) + (kp << 6) + n4) = u;
    }
}

// ---------------- K2: binning + tile table ----------------
__global__ __launch_bounds__(512) void bin_kernel() {
    int tid = threadIdx.x;
    int warp = tid >> 5, lane = tid & 31;
    int e = warp;
    __shared__ int scnt[E_NUM];
    __shared__ int sbase[E_NUM + 1];

    int cnt = 0;
    for (int base = 0; base < O_DIM; base += 32) {
        int r = base + lane;
        bool f = (g_topk_idx[r * 4 + 0] == e) || (g_topk_idx[r * 4 + 1] == e) ||
                 (g_topk_idx[r * 4 + 2] == e) || (g_topk_idx[r * 4 + 3] == e);
        unsigned m = __ballot_sync(0xffffffffu, f);
        cnt += __popc(m);
    }
    if (lane == 0) scnt[e] = cnt;
    __syncthreads();
    if (tid == 0) {
        int s = 0;
        for (int q = 0; q < E_NUM; q++) { sbase[q] = s; s += scnt[q]; }
        sbase[E_NUM] = s;
        int t = 0;
        for (int q = 0; q < E_NUM; q++)
            for (int m0 = 0; m0 < scnt[q]; m0 += 64) {
                g_tile_e[t] = q;
                g_tile_m0[t] = m0;
                t++;
            }
        g_ntile = t;
    }
    __syncthreads();
    if (tid < E_NUM + 1) g_base[tid] = sbase[tid];

    int off = sbase[e];
    for (int base = 0; base < O_DIM; base += 32) {
        int r = base + lane;
        int j = -1;
        if      (g_topk_idx[r * 4 + 0] == e) j = 0;
        else if (g_topk_idx[r * 4 + 1] == e) j = 1;
        else if (g_topk_idx[r * 4 + 2] == e) j = 2;
        else if (g_topk_idx[r * 4 + 3] == e) j = 3;
        bool f = (j >= 0);
        unsigned m = __ballot_sync(0xffffffffu, f);
        int pos = off + __popc(m & ((1u << lane) - 1u));
        if (f) {
            g_rows_sorted[pos] = r;
            g_pair_of[r * 4 + j] = pos;
        }
        off += __popc(m);
    }
}

// ============ fused kernel 2: fc1 + action + loss in one grid ==============
// fc1 B now staged as raw fp32 from w1, packed to f16x2 at fragment load.
// A stage: 64 rows x 80B = 5120 B
// B stage: 32 k-rows x 132 floats (128 + 4 pad) = 16896 B (conflict-free)
#define FC1_ASTAGE 5120
#define FC1_BSTAGE 16896
#define FC1_STG    (FC1_ASTAGE + FC1_BSTAGE)     // 22016
#define FC1_SMEM   (3 * FC1_STG + 256)           // 66304 -> 3 CTAs/SM
#define MEGA_GRID  (2305)

__device__ __forceinline__ void fc1_body(int nt, int tidx, const float* __restrict__ w1,
                                         const float* __restrict__ b1, char* smem) {
    if (tidx >= g_ntile) return;
    int e  = g_tile_e[tidx];
    int m0 = g_tile_m0[tidx];
    int pb = g_base[e];
    int ne = g_base[e + 1] - pb;

    uint32_t sb = smem_u32(smem);
    int tid = threadIdx.x;
    int lane = tid & 31, warp = tid >> 5;
    int wm = warp >> 2, wn = warp & 3;

    int* rowid = (int*)(smem + 3 * FC1_STG);
    if (tid < 64) {
        int mi = m0 + tid;
        rowid[tid] = g_rows_sorted[pb + (mi < ne ? mi : ne - 1)];
    }
    __syncthreads();

    int ar0 = tid >> 2, as0 = tid & 3;
    const char* ap0 = (const char*)g_obs_h + (size_t)rowid[ar0] * 2048 + as0 * 16;
    // B: 32 k-rows x 512 B = 1024 granules, 4 per thread
    int bk = tid >> 3, bns = tid & 7;
    const float* bptr = w1 + ((size_t)e << 21) + nt * 128 +
                        (size_t)bk * H_DIM + bns * 16;

    auto issue = [&](int st, int ch) {
        uint32_t s0 = sb + st * FC1_STG;
        cp_async16(s0 + ar0 * 80 + as0 * 16, ap0 + ch * 64);
        uint32_t sB = s0 + FC1_ASTAGE + bk * 528 + bns * 64;
        const float* bg = bptr + (size_t)ch * 32 * H_DIM;
#pragma unroll
        for (int q = 0; q < 4; q++) cp_async16(sB + q * 16, bg + q * 4);
        cp_commit();
    };

    float c[2][4][4];
#pragma unroll
    for (int i = 0; i < 2; i++)
#pragma unroll
        for (int j = 0; j < 4; j++)
#pragma unroll
            for (int q = 0; q < 4; q++) c[i][j][q] = 0.f;

    issue(0, 0);
    issue(1, 1);

    uint32_t aoff = (uint32_t)(wm * 32 + (lane & 15)) * 80 + (lane >> 4) * 16;
    int colb = wn * 32 + (lane >> 2);
    int krow2 = 2 * (lane & 3);

    for (int ch = 0; ch < 32; ch++) {
        if (ch < 31) cp_wait<1>(); else cp_wait<0>();
        __syncthreads();
        if (ch + 2 < 32) issue((ch + 2) % 3, ch + 2);

        uint32_t stg = sb + (ch % 3) * FC1_STG;
        const float* Bw = (const float*)(smem + (ch % 3) * FC1_STG + FC1_ASTAGE);

#pragma unroll
        for (int s = 0; s < 2; s++) {
            unsigned a[2][4];
#pragma unroll
            for (int i = 0; i < 2; i++)
                ldmatrix_x4(a[i], stg + aoff + i * 1280 + s * 32);
            unsigned b[4][2];
#pragma unroll
            for (int j = 0; j < 4; j++) {
                int col = colb + j * 8;
                int kb = s * 16 + krow2;
                b[j][0] = pack_f16x2(Bw[kb * 132 + col], Bw[(kb + 1) * 132 + col]);
                b[j][1] = pack_f16x2(Bw[(kb + 8) * 132 + col], Bw[(kb + 9) * 132 + col]);
            }
#pragma unroll
            for (int i = 0; i < 2; i++)
#pragma unroll
                for (int j = 0; j < 4; j++)
                    mma_f16(c[i][j], a[i][0], a[i][1], a[i][2], a[i][3], b[j][0], b[j][1]);
        }
    }

    const float* b1e = b1 + e * H_DIM + nt * 128;
#pragma unroll
    for (int i = 0; i < 2; i++) {
        int r0 = m0 + wm * 32 + i * 16 + (lane >> 2);
#pragma unroll
        for (int j = 0; j < 4; j++) {
            int cc = wn * 32 + j * 8 + 2 * (lane & 3);
            float bv0 = b1e[cc], bv1 = b1e[cc + 1];
            if (r0 < ne) {
                float y0 = fmaxf(c[i][j][0] + bv0, 0.f);
                float y1 = fmaxf(c[i][j][1] + bv1, 0.f);
                g_h[((size_t)(pb + r0) * H_DIM + nt * 128 + cc) >> 1] = pack_f16x2(y0, y1);
            }
            if (r0 + 8 < ne) {
                float y0 = fmaxf(c[i][j][2] + bv0, 0.f);
                float y1 = fmaxf(c[i][j][3] + bv1, 0.f);
                g_h[((size_t)(pb + r0 + 8) * H_DIM + nt * 128 + cc) >> 1] = pack_f16x2(y0, y1);
            }
        }
    }
}

__device__ __forceinline__ void action_body(int o, const float* __restrict__ obs,
                                            const float* __restrict__ lastw,
                                            const float* __restrict__ lastb,
                                            float* __restrict__ out, char* smem) {
    int tid = threadIdx.x;
    float* obsS = (float*)smem;
    float* red  = obsS + D_DIM;
    float* muS  = red + 16 * A_DIM;
    float* eS   = muS + A_DIM;

    obsS[tid]       = obs[(size_t)o * D_DIM + tid];
    obsS[tid + 256] = obs[(size_t)o * D_DIM + tid + 256];
    obsS[tid + 512] = obs[(size_t)o * D_DIM + tid + 512];
    obsS[tid + 768] = obs[(size_t)o * D_DIM + tid + 768];
    __syncthreads();

    int a4 = (tid & 15) * 4;
    int chunk = tid >> 4;

    const float* lw = lastw + (size_t)o * D_DIM * A_DIM + (size_t)chunk * 64 * A_DIM + a4;
    float ax = 0.f, ay = 0.f, az = 0.f, aw = 0.f;
#pragma unroll 8
    for (int d = 0; d < 64; d++) {
        float4 w = __ldcs(reinterpret_cast<const float4*>(lw + (size_t)d * A_DIM));
        float x = obsS[chunk * 64 + d];
        ax += x * w.x; ay += x * w.y; az += x * w.z; aw += x * w.w;
    }
    red[chunk * A_DIM + a4 + 0] = ax;
    red[chunk * A_DIM + a4 + 1] = ay;
    red[chunk * A_DIM + a4 + 2] = az;
    red[chunk * A_DIM + a4 + 3] = aw;
    __syncthreads();

    if (tid < A_DIM) {
        float m = 0.f;
        for (int c = 0; c < 16; c++) m += red[c * A_DIM + tid];
        muS[tid] = m + lastb[o * A_DIM + tid];
    }
    __syncthreads();
    if (tid < A_DIM) {
        float mx = muS[0];
        for (int i = 1; i < A_DIM; i++) mx = fmaxf(mx, muS[i]);
        float t  = muS[tid] - mx;
        float ef = expf(t);
        if (ef < FLT_MIN_NORM) ef = 0.f;         // FTZ emulation
        eS[tid] = ef;
    }
    __syncthreads();
    if (tid < A_DIM) {
        float ssum = 0.f;
        for (int i = 0; i < A_DIM; i++) ssum += eS[i];
        float p = eS[tid] / ssum;
        if (p < FLT_MIN_NORM) p = 0.f;           // FTZ emulation
        out[(size_t)o * A_DIM + tid] = p;
        float lp = (p == 0.f) ? logf(1e-8f) : logf(p);
        out[(size_t)O_DIM * A_DIM + o * A_DIM + tid] = lp;
    }
}

__device__ __forceinline__ void loss_body(float* __restrict__ out, char* smem) {
    int tid = threadIdx.x;
    float* sh = (float*)smem;
    float imp[4], ld[4];
#pragma unroll
    for (int q = 0; q < 4; q++) {
        imp[q] = g_importance[tid + q * 256];
        ld[q]  = g_load[tid + q * 256];
    }
    auto reduceSum = [&](float v) -> float {
#pragma unroll
        for (int o2 = 16; o2; o2 >>= 1) v += __shfl_xor_sync(0xffffffffu, v, o2);
        if ((tid & 31) == 0) sh[tid >> 5] = v;
        __syncthreads();
        if (tid < 32) {
            float r = (tid < 8) ? sh[tid] : 0.f;
#pragma unroll
            for (int o2 = 4; o2; o2 >>= 1) r += __shfl_xor_sync(0xffffffffu, r, o2);
            if (tid == 0) sh[8] = r;
        }
        __syncthreads();
        float r = sh[8];
        __syncthreads();
        return r;
    };

    float si = reduceSum(imp[0] + imp[1] + imp[2] + imp[3]);
    float mi = si / (float)O_DIM;
    float di = 0.f;
#pragma unroll
    for (int q = 0; q < 4; q++) { float d = imp[q] - mi; di += d * d; }
    float ssi = reduceSum(di);
    float sl = reduceSum(ld[0] + ld[1] + ld[2] + ld[3]);
    float ml = sl / (float)O_DIM;
    float dl = 0.f;
#pragma unroll
    for (int q = 0; q < 4; q++) { float d = ld[q] - ml; dl += d * d; }
    float ssl = reduceSum(dl);
    if (tid == 0) {
        float vi = ssi / (float)(O_DIM - 1);
        float vl = ssl / (float)(O_DIM - 1);
        float loss = (vi / (mi * mi + 1e-10f) + vl / (ml * ml + 1e-10f)) * 0.01f;
        out[3 * O_DIM * A_DIM] = loss;
    }
}

// grid 2305: groups of 9 blocks = 5 fc1 + 4 action; last block = loss.
__global__ __launch_bounds__(256, 3) void mega_kernel(const float* __restrict__ w1,
                                                      const float* __restrict__ b1,
                                                      const float* __restrict__ obs,
                                                      const float* __restrict__ lastw,
                                                      const float* __restrict__ lastb,
                                                      float* __restrict__ out) {
    extern __shared__ char smem[];
    int bid = blockIdx.x;
    if (bid == MEGA_GRID - 1) { loss_body(out, smem); return; }
    int g = bid / 9, r = bid % 9;
    if (r < 5) {
        int fid = g * 5 + r;
        fc1_body(fid & 15, fid >> 4, w1, b1, smem);
    } else {
        action_body(g * 4 + (r - 5), obs, lastw, lastb, out, smem);
    }
}

// ---------------- fc2 grouped GEMM (fp16, ldmatrix, K-split 4) -------------
#define FC2_ASTAGE 5120
#define FC2_BSTAGE 4608
#define FC2_STG    (FC2_ASTAGE + FC2_BSTAGE)
#define FC2_SMEM   (3 * FC2_STG)

__global__ __launch_bounds__(256) void expert_fc2_kernel() {
    int ks = blockIdx.x, tidx = blockIdx.y;
    if (tidx >= g_ntile) return;
    int e  = g_tile_e[tidx];
    int m0 = g_tile_m0[tidx];
    int pb = g_base[e];
    int ne = g_base[e + 1] - pb;
    int kp0 = ks * 256;

    extern __shared__ char smem[];
    uint32_t sb = smem_u32(smem);
    int tid = threadIdx.x;
    int lane = tid & 31, warp = tid >> 5;
    int wm = warp >> 2, wn = warp & 3;

    int ar = tid >> 2, as = tid & 3;
    int rowc = pb + m0 + ar;
    if (rowc > NPAIR - 1) rowc = NPAIR - 1;
    const char* ap = (const char*)g_h + (size_t)rowc * 4096 + kp0 * 4 + as * 16;
    int bkp = tid >> 4, bns = tid & 15;
    const char* bp = (const char*)g_w2p +
                     (((size_t)e << 16) + (size_t)(kp0 + bkp) * 64 + bns * 4) * 4;

    auto issue = [&](int st, int ch) {
        uint32_t s0 = sb + st * FC2_STG;
        cp_async16(s0 + ar * 80 + as * 16, ap + ch * 64);
        cp_async16(s0 + FC2_ASTAGE + bkp * 288 + bns * 16, bp + (size_t)ch * 16 * 256);
        cp_commit();
    };

    float c[2][2][4];
#pragma unroll
    for (int i = 0; i < 2; i++)
#pragma unroll
        for (int j = 0; j < 2; j++)
#pragma unroll
            for (int q = 0; q < 4; q++) c[i][j][q] = 0.f;

    issue(0, 0);
    issue(1, 1);

    uint32_t aoff = (uint32_t)(wm * 32 + (lane & 15)) * 80 + (lane >> 4) * 16;
    int colb = wn * 16 + (lane >> 2);
    int krow = lane & 3;

    for (int ch = 0; ch < 16; ch++) {
        if (ch < 15) cp_wait<1>(); else cp_wait<0>();
        __syncthreads();
        if (ch + 2 < 16) issue((ch + 2) % 3, ch + 2);

        uint32_t stg = sb + (ch % 3) * FC2_STG;
        const unsigned* Bp = (const unsigned*)(smem + (ch % 3) * FC2_STG + FC2_ASTAGE);

#pragma unroll
        for (int s = 0; s < 2; s++) {
            unsigned a[2][4];
#pragma unroll
            for (int i = 0; i < 2; i++)
                ldmatrix_x4(a[i], stg + aoff + i * 1280 + s * 32);
            unsigned b[2][2];
#pragma unroll
            for (int j = 0; j < 2; j++) {
                int w0 = (s * 8 + krow) * 72 + colb + j * 8;
                b[j][0] = Bp[w0];
                b[j][1] = Bp[w0 + 288];
            }
#pragma unroll
            for (int i = 0; i < 2; i++)
#pragma unroll
                for (int j = 0; j < 2; j++)
                    mma_f16(c[i][j], a[i][0], a[i][1], a[i][2], a[i][3], b[j][0], b[j][1]);
        }
    }

    float* zp = g_z + (size_t)ks * NPAIR * A_DIM;
#pragma unroll
    for (int i = 0; i < 2; i++) {
        int r0 = m0 + wm * 32 + i * 16 + (lane >> 2);
#pragma unroll
        for (int j = 0; j < 2; j++) {
            int c0 = wn * 16 + j * 8 + 2 * (lane & 3);
            if (r0 < ne) {
                float* dst = zp + (size_t)(pb + r0) * A_DIM + c0;
                dst[0] = c[i][j][0];
                dst[1] = c[i][j][1];
            }
            if (r0 + 8 < ne) {
                float* dst = zp + (size_t)(pb + r0 + 8) * A_DIM + c0;
                dst[0] = c[i][j][2];
                dst[1] = c[i][j][3];
            }
        }
    }
}

// ---------------- combine (sums 4 k-slice partials) ----------------
__global__ __launch_bounds__(256) void combine_kernel(const float* __restrict__ b2,
                                                      float* __restrict__ out) {
    int i = blockIdx.x * blockDim.x + threadIdx.x;
    if (i >= O_DIM * A_DIM) return;
    int o = i >> 6, a = i & 63;
    float y = 0.f;
#pragma unroll
    for (int j = 0; j < TOPK; j++) {
        int eidx = g_topk_idx[o * TOPK + j];
        float g  = g_topk_gate[o * TOPK + j];
        int p    = g_pair_of[o * TOPK + j];
        size_t base = (size_t)p * A_DIM + a;
        float z = g_z[base] + g_z[base + (size_t)NPAIR * A_DIM] +
                  g_z[base + 2 * (size_t)NPAIR * A_DIM] + g_z[base + 3 * (size_t)NPAIR * A_DIM];
        y += g * (z + b2[eidx * A_DIM + a]);
    }
    out[2 * O_DIM * A_DIM + i] = y;
}

// ---------------- launch ----------------------------------------------------
extern "C" void kernel_launch(void* const* d_in, const int* in_sizes, int n_in,
                              void* d_out, int out_size) {
    const float* obs   = (const float*)d_in[0];
    const float* wgate = (const float*)d_in[1];
    const float* w1    = (const float*)d_in[2];
    const float* b1    = (const float*)d_in[3];
    const float* w2    = (const float*)d_in[4];
    const float* b2    = (const float*)d_in[5];
    const float* lastw = (const float*)d_in[6];
    const float* lastb = (const float*)d_in[7];
    float* out = (float*)d_out;

    static int smem_set = 0;
    if (!smem_set) {
        cudaFuncSetAttribute(mega_kernel,
                             cudaFuncAttributeMaxDynamicSharedMemorySize, FC1_SMEM);
        cudaFuncSetAttribute(expert_fc2_kernel,
                             cudaFuncAttributeMaxDynamicSharedMemorySize, FC2_SMEM);
        smem_set = 1;
    }

    prep_gate_kernel<<<O_DIM + PREP_BLOCKS, 256>>>(obs, wgate, w2);
    bin_kernel<<<1, 512>>>();
    mega_kernel<<<MEGA_GRID, 256, FC1_SMEM>>>(w1, b1, obs, lastw, lastb, out);
    expert_fc2_kernel<<<dim3(4, MAXTILE), 256, FC2_SMEM>>>();
    combine_kernel<<<(O_DIM * A_DIM + 255) / 256, 256>>>(b2, out);
}

// round 14
// speedup vs baseline: 1.4389x; 1.4389x over previous
#include <cuda_runtime.h>
#include <cuda_bf16.h>
#include <math.h>
#include <stdint.h>

#define O_DIM 1024
#define D_DIM 1024
#define E_NUM 16
#define TOPK  4
#define H_DIM 2048
#define A_DIM 64
#define NPAIR (O_DIM * TOPK)
#define FLT_MIN_NORM 1.17549435e-38f
#define MAXTILE 80
#define KSPLIT 8

// ---------------- scratch (static device memory; no allocs) ----------------
__device__ int      g_topk_idx[NPAIR];
__device__ float    g_topk_gate[NPAIR];
__device__ float    g_importance[O_DIM];
__device__ float    g_load[O_DIM];
__device__ int      g_base[E_NUM + 1];
__device__ int      g_rows_sorted[NPAIR];
__device__ int      g_pair_of[NPAIR];
__device__ int      g_ntile;
__device__ int      g_tile_e[MAXTILE];
__device__ int      g_tile_m0[MAXTILE];
__device__ unsigned g_obs_h[O_DIM * D_DIM / 2];
__device__ unsigned g_w1p[E_NUM * (D_DIM / 2) * H_DIM];
__device__ unsigned g_w2p[E_NUM * (H_DIM / 2) * A_DIM];
__device__ unsigned g_h[NPAIR * H_DIM / 2];
__device__ float    g_z[KSPLIT * NPAIR * A_DIM];

#define N_OBS4 (O_DIM * D_DIM / 8)
#define N_W14  (E_NUM * (D_DIM / 2) * H_DIM / 4)
#define N_W24  (E_NUM * (H_DIM / 2) * A_DIM / 4)
#define PREP_BLOCKS ((N_OBS4 + N_W14 + N_W24) / 256)   // 17920

// ---------------- helpers ----------------
__device__ __forceinline__ uint32_t smem_u32(const void* p) {
    uint32_t a;
    asm("{ .reg .u64 t; cvta.to.shared.u64 t, %1; cvt.u32.u64 %0, t; }" : "=r"(a) : "l"(p));
    return a;
}
__device__ __forceinline__ void cp_async16(uint32_t saddr, const void* gptr) {
    asm volatile("cp.async.cg.shared.global [%0], [%1], 16;" :: "r"(saddr), "l"(gptr));
}
__device__ __forceinline__ void cp_commit() {
    asm volatile("cp.async.commit_group;" ::: "memory");
}
template <int N> __device__ __forceinline__ void cp_wait() {
    asm volatile("cp.async.wait_group %0;" :: "n"(N) : "memory");
}
__device__ __forceinline__ unsigned pack_f16x2(float lo, float hi) {
    unsigned u;
    asm("cvt.rn.f16x2.f32 %0, %1, %2;" : "=r"(u) : "f"(hi), "f"(lo));
    return u;
}
__device__ __forceinline__ void ldmatrix_x4(unsigned r[4], uint32_t saddr) {
    asm volatile("ldmatrix.sync.aligned.m8n8.x4.shared.b16 {%0,%1,%2,%3}, [%4];"
                 : "=r"(r[0]), "=r"(r[1]), "=r"(r[2]), "=r"(r[3]) : "r"(saddr));
}
__device__ __forceinline__ void mma_f16(float c[4], unsigned a0, unsigned a1,
                                        unsigned a2, unsigned a3,
                                        unsigned b0, unsigned b1) {
    asm volatile(
        "mma.sync.aligned.m16n8k16.row.col.f32.f16.f16.f32 "
        "{%0,%1,%2,%3}, {%4,%5,%6,%7}, {%8,%9}, {%0,%1,%2,%3};\n"
        : "+f"(c[0]), "+f"(c[1]), "+f"(c[2]), "+f"(c[3])
        : "r"(a0), "r"(a1), "r"(a2), "r"(a3), "r"(b0), "r"(b1));
}

// ============ fused kernel 1: gate (blocks 0..1023) + prep (rest) ==========
__global__ __launch_bounds__(256) void prep_gate_kernel(const float* __restrict__ obs,
                                                        const float* __restrict__ wg,
                                                        const float* __restrict__ w1,
                                                        const float* __restrict__ w2) {
    int bid = blockIdx.x;
    int tid = threadIdx.x;

    if (bid < O_DIM) {
        int o = bid;
        const float* wrow = wg + (size_t)o * D_DIM * E_NUM;
        const float* orow = obs + (size_t)o * D_DIM;

        float acc[E_NUM];
#pragma unroll
        for (int i = 0; i < E_NUM; i++) acc[i] = 0.f;
        for (int d = tid; d < D_DIM; d += 256) {
            float x = orow[d];
            const float4* p = reinterpret_cast<const float4*>(wrow + (size_t)d * E_NUM);
            float4 v0 = p[0], v1 = p[1], v2 = p[2], v3 = p[3];
            acc[0]  += x * v0.x; acc[1]  += x * v0.y; acc[2]  += x * v0.z; acc[3]  += x * v0.w;
            acc[4]  += x * v1.x; acc[5]  += x * v1.y; acc[6]  += x * v1.z; acc[7]  += x * v1.w;
            acc[8]  += x * v2.x; acc[9]  += x * v2.y; acc[10] += x * v2.z; acc[11] += x * v2.w;
            acc[12] += x * v3.x; acc[13] += x * v3.y; acc[14] += x * v3.z; acc[15] += x * v3.w;
        }
#pragma unroll
        for (int i = 0; i < E_NUM; i++) {
#pragma unroll
            for (int off = 16; off; off >>= 1)
                acc[i] += __shfl_xor_sync(0xffffffffu, acc[i], off);
        }
        __shared__ float s[8][E_NUM];
        int warp = tid >> 5, lane = tid & 31;
        if (lane == 0) {
#pragma unroll
            for (int i = 0; i < E_NUM; i++) s[warp][i] = acc[i];
        }
        __syncthreads();
        if (tid == 0) {
            float logit[E_NUM];
            for (int e = 0; e < E_NUM; e++) {
                float t = 0.f;
                for (int w = 0; w < 8; w++) t += s[w][e];
                logit[e] = t;
            }
            bool taken[E_NUM];
            for (int e = 0; e < E_NUM; e++) taken[e] = false;
            int idx[TOPK]; float val[TOPK];
            for (int k = 0; k < TOPK; k++) {
                float best = -3.4e38f; int bi = 0;
                for (int e = 0; e < E_NUM; e++)
                    if (!taken[e] && logit[e] > best) { best = logit[e]; bi = e; }
                taken[bi] = true; idx[k] = bi; val[k] = best;
            }
            float m = val[0];
            float ex[TOPK]; float se = 0.f;
            for (int k = 0; k < TOPK; k++) { ex[k] = expf(val[k] - m); se += ex[k]; }
            float gates[E_NUM];
            for (int e = 0; e < E_NUM; e++) gates[e] = 0.f;
            for (int k = 0; k < TOPK; k++) gates[idx[k]] = ex[k] / se;
            float imp = 0.f; int ldc = 0;
            for (int e = 0; e < E_NUM; e++) { imp += gates[e]; ldc += (gates[e] > 0.f); }
            for (int k = 0; k < TOPK; k++) {
                g_topk_idx[o * TOPK + k]  = idx[k];
                g_topk_gate[o * TOPK + k] = gates[idx[k]];
            }
            g_importance[o] = imp;
            g_load[o] = (float)ldc;
        }
        return;
    }

    int idx = (bid - O_DIM) * 256 + tid;
    if (idx < N_OBS4) {
        const float4* p = reinterpret_cast<const float4*>(obs) + idx * 2;
        float4 f0 = p[0], f1 = p[1];
        uint4 u;
        u.x = pack_f16x2(f0.x, f0.y);
        u.y = pack_f16x2(f0.z, f0.w);
        u.z = pack_f16x2(f1.x, f1.y);
        u.w = pack_f16x2(f1.z, f1.w);
        reinterpret_cast<uint4*>(g_obs_h)[idx] = u;
    } else if (idx < N_OBS4 + N_W14) {
        int t = idx - N_OBS4;
        int e  = t >> 18;
        int r  = t & 262143;
        int kp = r >> 9;
        int n4 = (r & 511) * 4;
        const float* p = w1 + ((size_t)e << 21) + ((size_t)kp << 12) + n4;
        float4 f0 = __ldcs(reinterpret_cast<const float4*>(p));
        float4 f1 = __ldcs(reinterpret_cast<const float4*>(p + 2048));
        uint4 u;
        u.x = pack_f16x2(f0.x, f1.x);
        u.y = pack_f16x2(f0.y, f1.y);
        u.z = pack_f16x2(f0.z, f1.z);
        u.w = pack_f16x2(f0.w, f1.w);
        *reinterpret_cast<uint4*>(g_w1p + ((size_t)e << 20) + (kp << 11) + n4) = u;
    } else if (idx < N_OBS4 + N_W14 + N_W24) {
        int t = idx - (N_OBS4 + N_W14);
        int e  = t >> 14;
        int r  = t & 16383;
        int kp = r >> 4;
        int n4 = (r & 15) * 4;
        const float* p = w2 + ((size_t)e << 17) + (kp << 7) + n4;
        float4 f0 = __ldcs(reinterpret_cast<const float4*>(p));
        float4 f1 = __ldcs(reinterpret_cast<const float4*>(p + 64));
        uint4 u;
        u.x = pack_f16x2(f0.x, f1.x);
        u.y = pack_f16x2(f0.y, f1.y);
        u.z = pack_f16x2(f0.z, f1.z);
        u.w = pack_f16x2(f0.w, f1.w);
        *reinterpret_cast<uint4*>(g_w2p + ((size_t)e << 16) + (kp << 6) + n4) = u;
    }
}

// ---------------- K2: binning + tile table ----------------
__global__ __launch_bounds__(512) void bin_kernel() {
    int tid = threadIdx.x;
    int warp = tid >> 5, lane = tid & 31;
    int e = warp;
    __shared__ int scnt[E_NUM];
    __shared__ int sbase[E_NUM + 1];

    int cnt = 0;
    for (int base = 0; base < O_DIM; base += 32) {
        int r = base + lane;
        bool f = (g_topk_idx[r * 4 + 0] == e) || (g_topk_idx[r * 4 + 1] == e) ||
                 (g_topk_idx[r * 4 + 2] == e) || (g_topk_idx[r * 4 + 3] == e);
        unsigned m = __ballot_sync(0xffffffffu, f);
        cnt += __popc(m);
    }
    if (lane == 0) scnt[e] = cnt;
    __syncthreads();
    if (tid == 0) {
        int s = 0;
        for (int q = 0; q < E_NUM; q++) { sbase[q] = s; s += scnt[q]; }
        sbase[E_NUM] = s;
        int t = 0;
        for (int q = 0; q < E_NUM; q++)
            for (int m0 = 0; m0 < scnt[q]; m0 += 64) {
                g_tile_e[t] = q;
                g_tile_m0[t] = m0;
                t++;
            }
        g_ntile = t;
    }
    __syncthreads();
    if (tid < E_NUM + 1) g_base[tid] = sbase[tid];

    int off = sbase[e];
    for (int base = 0; base < O_DIM; base += 32) {
        int r = base + lane;
        int j = -1;
        if      (g_topk_idx[r * 4 + 0] == e) j = 0;
        else if (g_topk_idx[r * 4 + 1] == e) j = 1;
        else if (g_topk_idx[r * 4 + 2] == e) j = 2;
        else if (g_topk_idx[r * 4 + 3] == e) j = 3;
        bool f = (j >= 0);
        unsigned m = __ballot_sync(0xffffffffu, f);
        int pos = off + __popc(m & ((1u << lane) - 1u));
        if (f) {
            g_rows_sorted[pos] = r;
            g_pair_of[r * 4 + j] = pos;
        }
        off += __popc(m);
    }
}

// ============ fused kernel 2: fc1 + action + loss in one grid ==============
#define FC1_ASTAGE 5120
#define FC1_BSTAGE 8704
#define FC1_STG    (FC1_ASTAGE + FC1_BSTAGE)
#define FC1_SMEM   (3 * FC1_STG + 256)
#define MEGA_GRID  (2305)   // 256*9 fc1/action groups + 1 loss

__device__ __forceinline__ void fc1_body(int nt, int tidx, const float* __restrict__ b1,
                                         char* smem) {
    if (tidx >= g_ntile) return;
    int e  = g_tile_e[tidx];
    int m0 = g_tile_m0[tidx];
    int pb = g_base[e];
    int ne = g_base[e + 1] - pb;

    uint32_t sb = smem_u32(smem);
    int tid = threadIdx.x;
    int lane = tid & 31, warp = tid >> 5;
    int wm = warp >> 2, wn = warp & 3;

    int* rowid = (int*)(smem + 3 * FC1_STG);
    if (tid < 64) {
        int mi = m0 + tid;
        rowid[tid] = g_rows_sorted[pb + (mi < ne ? mi : ne - 1)];
    }
    __syncthreads();

    int ar0 = tid >> 2, as0 = tid & 3;
    const char* ap0 = (const char*)g_obs_h + (size_t)rowid[ar0] * 2048 + as0 * 16;
    int bkp = tid >> 5, bns = tid & 31;
    const char* bp = (const char*)g_w1p +
                     (((size_t)e << 20) + nt * 128 + bns * 4) * 4;

    auto issue = [&](int st, int ch) {
        uint32_t s0 = sb + st * FC1_STG;
        cp_async16(s0 + ar0 * 80 + as0 * 16, ap0 + ch * 64);
        uint32_t sB = s0 + FC1_ASTAGE + bns * 16;
        cp_async16(sB + bkp * 544, bp + (size_t)(ch * 16 + bkp) * 8192);
        cp_async16(sB + (bkp + 8) * 544, bp + (size_t)(ch * 16 + bkp + 8) * 8192);
        cp_commit();
    };

    float c[2][4][4];
#pragma unroll
    for (int i = 0; i < 2; i++)
#pragma unroll
        for (int j = 0; j < 4; j++)
#pragma unroll
            for (int q = 0; q < 4; q++) c[i][j][q] = 0.f;

    issue(0, 0);
    issue(1, 1);

    uint32_t aoff = (uint32_t)(wm * 32 + (lane & 15)) * 80 + (lane >> 4) * 16;
    int colb = wn * 32 + (lane >> 2);
    int krow = lane & 3;

    for (int ch = 0; ch < 32; ch++) {
        if (ch < 31) cp_wait<1>(); else cp_wait<0>();
        __syncthreads();
        if (ch + 2 < 32) issue((ch + 2) % 3, ch + 2);

        uint32_t stg = sb + (ch % 3) * FC1_STG;
        const unsigned* Bp = (const unsigned*)(smem + (ch % 3) * FC1_STG + FC1_ASTAGE);

#pragma unroll
        for (int s = 0; s < 2; s++) {
            unsigned a[2][4];
#pragma unroll
            for (int i = 0; i < 2; i++)
                ldmatrix_x4(a[i], stg + aoff + i * 1280 + s * 32);
            unsigned b[4][2];
#pragma unroll
            for (int j = 0; j < 4; j++) {
                int w0 = (s * 8 + krow) * 136 + colb + j * 8;
                b[j][0] = Bp[w0];
                b[j][1] = Bp[w0 + 544];
            }
#pragma unroll
            for (int i = 0; i < 2; i++)
#pragma unroll
                for (int j = 0; j < 4; j++)
                    mma_f16(c[i][j], a[i][0], a[i][1], a[i][2], a[i][3], b[j][0], b[j][1]);
        }
    }

    const float* b1e = b1 + e * H_DIM + nt * 128;
#pragma unroll
    for (int i = 0; i < 2; i++) {
        int r0 = m0 + wm * 32 + i * 16 + (lane >> 2);
#pragma unroll
        for (int j = 0; j < 4; j++) {
            int cc = wn * 32 + j * 8 + 2 * (lane & 3);
            float bv0 = b1e[cc], bv1 = b1e[cc + 1];
            if (r0 < ne) {
                float y0 = fmaxf(c[i][j][0] + bv0, 0.f);
                float y1 = fmaxf(c[i][j][1] + bv1, 0.f);
                g_h[((size_t)(pb + r0) * H_DIM + nt * 128 + cc) >> 1] = pack_f16x2(y0, y1);
            }
            if (r0 + 8 < ne) {
                float y0 = fmaxf(c[i][j][2] + bv0, 0.f);
                float y1 = fmaxf(c[i][j][3] + bv1, 0.f);
                g_h[((size_t)(pb + r0 + 8) * H_DIM + nt * 128 + cc) >> 1] = pack_f16x2(y0, y1);
            }
        }
    }
}

__device__ __forceinline__ void action_body(int o, const float* __restrict__ obs,
                                            const float* __restrict__ lastw,
                                            const float* __restrict__ lastb,
                                            float* __restrict__ out, char* smem) {
    int tid = threadIdx.x;
    float* obsS = (float*)smem;
    float* red  = obsS + D_DIM;
    float* muS  = red + 16 * A_DIM;
    float* eS   = muS + A_DIM;

    obsS[tid]       = obs[(size_t)o * D_DIM + tid];
    obsS[tid + 256] = obs[(size_t)o * D_DIM + tid + 256];
    obsS[tid + 512] = obs[(size_t)o * D_DIM + tid + 512];
    obsS[tid + 768] = obs[(size_t)o * D_DIM + tid + 768];
    __syncthreads();

    int a4 = (tid & 15) * 4;
    int chunk = tid >> 4;

    const float* lw = lastw + (size_t)o * D_DIM * A_DIM + (size_t)chunk * 64 * A_DIM + a4;
    float ax = 0.f, ay = 0.f, az = 0.f, aw = 0.f;
#pragma unroll 8
    for (int d = 0; d < 64; d++) {
        float4 w = __ldcs(reinterpret_cast<const float4*>(lw + (size_t)d * A_DIM));
        float x = obsS[chunk * 64 + d];
        ax += x * w.x; ay += x * w.y; az += x * w.z; aw += x * w.w;
    }
    red[chunk * A_DIM + a4 + 0] = ax;
    red[chunk * A_DIM + a4 + 1] = ay;
    red[chunk * A_DIM + a4 + 2] = az;
    red[chunk * A_DIM + a4 + 3] = aw;
    __syncthreads();

    if (tid < A_DIM) {
        float m = 0.f;
        for (int c = 0; c < 16; c++) m += red[c * A_DIM + tid];
        muS[tid] = m + lastb[o * A_DIM + tid];
    }
    __syncthreads();
    if (tid < A_DIM) {
        float mx = muS[0];
        for (int i = 1; i < A_DIM; i++) mx = fmaxf(mx, muS[i]);
        float t  = muS[tid] - mx;
        float ef = expf(t);
        if (ef < FLT_MIN_NORM) ef = 0.f;         // FTZ emulation
        eS[tid] = ef;
    }
    __syncthreads();
    if (tid < A_DIM) {
        float ssum = 0.f;
        for (int i = 0; i < A_DIM; i++) ssum += eS[i];
        float p = eS[tid] / ssum;
        if (p < FLT_MIN_NORM) p = 0.f;           // FTZ emulation
        out[(size_t)o * A_DIM + tid] = p;
        float lp = (p == 0.f) ? logf(1e-8f) : logf(p);
        out[(size_t)O_DIM * A_DIM + o * A_DIM + tid] = lp;
    }
}

__device__ __forceinline__ void loss_body(float* __restrict__ out, char* smem) {
    int tid = threadIdx.x;
    float* sh = (float*)smem;
    float imp[4], ld[4];
#pragma unroll
    for (int q = 0; q < 4; q++) {
        imp[q] = g_importance[tid + q * 256];
        ld[q]  = g_load[tid + q * 256];
    }
    auto reduceSum = [&](float v) -> float {
#pragma unroll
        for (int o2 = 16; o2; o2 >>= 1) v += __shfl_xor_sync(0xffffffffu, v, o2);
        if ((tid & 31) == 0) sh[tid >> 5] = v;
        __syncthreads();
        if (tid < 32) {
            float r = (tid < 8) ? sh[tid] : 0.f;
#pragma unroll
            for (int o2 = 4; o2; o2 >>= 1) r += __shfl_xor_sync(0xffffffffu, r, o2);
            if (tid == 0) sh[8] = r;
        }
        __syncthreads();
        float r = sh[8];
        __syncthreads();
        return r;
    };

    float si = reduceSum(imp[0] + imp[1] + imp[2] + imp[3]);
    float mi = si / (float)O_DIM;
    float di = 0.f;
#pragma unroll
    for (int q = 0; q < 4; q++) { float d = imp[q] - mi; di += d * d; }
    float ssi = reduceSum(di);
    float sl = reduceSum(ld[0] + ld[1] + ld[2] + ld[3]);
    float ml = sl / (float)O_DIM;
    float dl = 0.f;
#pragma unroll
    for (int q = 0; q < 4; q++) { float d = ld[q] - ml; dl += d * d; }
    float ssl = reduceSum(dl);
    if (tid == 0) {
        float vi = ssi / (float)(O_DIM - 1);
        float vl = ssl / (float)(O_DIM - 1);
        float loss = (vi / (mi * mi + 1e-10f) + vl / (ml * ml + 1e-10f)) * 0.01f;
        out[3 * O_DIM * A_DIM] = loss;
    }
}

// grid 2305: groups of 9 blocks = 5 fc1 + 4 action; last block = loss.
__global__ __launch_bounds__(256, 3) void mega_kernel(const float* __restrict__ b1,
                                                      const float* __restrict__ obs,
                                                      const float* __restrict__ lastw,
                                                      const float* __restrict__ lastb,
                                                      float* __restrict__ out) {
    extern __shared__ char smem[];
    int bid = blockIdx.x;
    if (bid == MEGA_GRID - 1) { loss_body(out, smem); return; }
    int g = bid / 9, r = bid % 9;
    if (r < 5) {
        int fid = g * 5 + r;
        fc1_body(fid & 15, fid >> 4, b1, smem);
    } else {
        action_body(g * 4 + (r - 5), obs, lastw, lastb, out, smem);
    }
}

// ---------------- fc2 grouped GEMM (fp16, ldmatrix, K-split 8) -------------
#define FC2_ASTAGE 5120
#define FC2_BSTAGE 4608
#define FC2_STG    (FC2_ASTAGE + FC2_BSTAGE)
#define FC2_SMEM   (3 * FC2_STG)

__global__ __launch_bounds__(256) void expert_fc2_kernel() {
    int ks = blockIdx.x, tidx = blockIdx.y;
    if (tidx >= g_ntile) return;
    int e  = g_tile_e[tidx];
    int m0 = g_tile_m0[tidx];
    int pb = g_base[e];
    int ne = g_base[e + 1] - pb;
    int kp0 = ks * 128;                          // 1024 kp / 8 slices

    extern __shared__ char smem[];
    uint32_t sb = smem_u32(smem);
    int tid = threadIdx.x;
    int lane = tid & 31, warp = tid >> 5;
    int wm = warp >> 2, wn = warp & 3;

    int ar = tid >> 2, as = tid & 3;
    int rowc = pb + m0 + ar;
    if (rowc > NPAIR - 1) rowc = NPAIR - 1;
    const char* ap = (const char*)g_h + (size_t)rowc * 4096 + kp0 * 4 + as * 16;
    int bkp = tid >> 4, bns = tid & 15;
    const char* bp = (const char*)g_w2p +
                     (((size_t)e << 16) + (size_t)(kp0 + bkp) * 64 + bns * 4) * 4;

    auto issue = [&](int st, int ch) {
        uint32_t s0 = sb + st * FC2_STG;
        cp_async16(s0 + ar * 80 + as * 16, ap + ch * 64);
        cp_async16(s0 + FC2_ASTAGE + bkp * 288 + bns * 16, bp + (size_t)ch * 16 * 256);
        cp_commit();
    };

    float c[2][2][4];
#pragma unroll
    for (int i = 0; i < 2; i++)
#pragma unroll
        for (int j = 0; j < 2; j++)
#pragma unroll
            for (int q = 0; q < 4; q++) c[i][j][q] = 0.f;

    issue(0, 0);
    issue(1, 1);

    uint32_t aoff = (uint32_t)(wm * 32 + (lane & 15)) * 80 + (lane >> 4) * 16;
    int colb = wn * 16 + (lane >> 2);
    int krow = lane & 3;

    for (int ch = 0; ch < 8; ch++) {
        if (ch < 7) cp_wait<1>(); else cp_wait<0>();
        __syncthreads();
        if (ch + 2 < 8) issue((ch + 2) % 3, ch + 2);

        uint32_t stg = sb + (ch % 3) * FC2_STG;
        const unsigned* Bp = (const unsigned*)(smem + (ch % 3) * FC2_STG + FC2_ASTAGE);

#pragma unroll
        for (int s = 0; s < 2; s++) {
            unsigned a[2][4];
#pragma unroll
            for (int i = 0; i < 2; i++)
                ldmatrix_x4(a[i], stg + aoff + i * 1280 + s * 32);
            unsigned b[2][2];
#pragma unroll
            for (int j = 0; j < 2; j++) {
                int w0 = (s * 8 + krow) * 72 + colb + j * 8;
                b[j][0] = Bp[w0];
                b[j][1] = Bp[w0 + 288];
            }
#pragma unroll
            for (int i = 0; i < 2; i++)
#pragma unroll
                for (int j = 0; j < 2; j++)
                    mma_f16(c[i][j], a[i][0], a[i][1], a[i][2], a[i][3], b[j][0], b[j][1]);
        }
    }

    float* zp = g_z + (size_t)ks * NPAIR * A_DIM;
#pragma unroll
    for (int i = 0; i < 2; i++) {
        int r0 = m0 + wm * 32 + i * 16 + (lane >> 2);
#pragma unroll
        for (int j = 0; j < 2; j++) {
            int c0 = wn * 16 + j * 8 + 2 * (lane & 3);
            if (r0 < ne) {
                float* dst = zp + (size_t)(pb + r0) * A_DIM + c0;
                dst[0] = c[i][j][0];
                dst[1] = c[i][j][1];
            }
            if (r0 + 8 < ne) {
                float* dst = zp + (size_t)(pb + r0 + 8) * A_DIM + c0;
                dst[0] = c[i][j][2];
                dst[1] = c[i][j][3];
            }
        }
    }
}

// ---------------- combine (sums 8 k-slice partials) ----------------
__global__ __launch_bounds__(256) void combine_kernel(const float* __restrict__ b2,
                                                      float* __restrict__ out) {
    int i = blockIdx.x * blockDim.x + threadIdx.x;
    if (i >= O_DIM * A_DIM) return;
    int o = i >> 6, a = i & 63;
    float y = 0.f;
#pragma unroll
    for (int j = 0; j < TOPK; j++) {
        int eidx = g_topk_idx[o * TOPK + j];
        float g  = g_topk_gate[o * TOPK + j];
        int p    = g_pair_of[o * TOPK + j];
        size_t base = (size_t)p * A_DIM + a;
        float z = 0.f;
#pragma unroll
        for (int q = 0; q < KSPLIT; q++)
            z += g_z[base + (size_t)q * NPAIR * A_DIM];
        y += g * (z + b2[eidx * A_DIM + a]);
    }
    out[2 * O_DIM * A_DIM + i] = y;
}

// ---------------- launch ----------------------------------------------------
extern "C" void kernel_launch(void* const* d_in, const int* in_sizes, int n_in,
                              void* d_out, int out_size) {
    const float* obs   = (const float*)d_in[0];
    const float* wgate = (const float*)d_in[1];
    const float* w1    = (const float*)d_in[2];
    const float* b1    = (const float*)d_in[3];
    const float* w2    = (const float*)d_in[4];
    const float* b2    = (const float*)d_in[5];
    const float* lastw = (const float*)d_in[6];
    const float* lastb = (const float*)d_in[7];
    float* out = (float*)d_out;

    static int smem_set = 0;
    if (!smem_set) {
        cudaFuncSetAttribute(mega_kernel,
                             cudaFuncAttributeMaxDynamicSharedMemorySize, FC1_SMEM);
        cudaFuncSetAttribute(expert_fc2_kernel,
                             cudaFuncAttributeMaxDynamicSharedMemorySize, FC2_SMEM);
        smem_set = 1;
    }

    prep_gate_kernel<<<O_DIM + PREP_BLOCKS, 256>>>(obs, wgate, w1, w2);
    bin_kernel<<<1, 512>>>();
    mega_kernel<<<MEGA_GRID, 256, FC1_SMEM>>>(b1, obs, lastw, lastb, out);
    expert_fc2_kernel<<<dim3(KSPLIT, MAXTILE), 256, FC2_SMEM>>>();
    combine_kernel<<<(O_DIM * A_DIM + 255) / 256, 256>>>(b2, out);
}

// round 15
// speedup vs baseline: 1.4519x; 1.0091x over previous
#include <cuda_runtime.h>
#include <cuda_bf16.h>
#include <math.h>
#include <stdint.h>

#define O_DIM 1024
#define D_DIM 1024
#define E_NUM 16
#define TOPK  4
#define H_DIM 2048
#define A_DIM 64
#define NPAIR (O_DIM * TOPK)
#define FLT_MIN_NORM 1.17549435e-38f
#define MAXTILE 80
#define KSPLIT 8

// ---------------- scratch (static device memory; no allocs) ----------------
__device__ int      g_topk_idx[NPAIR];
__device__ float    g_topk_gate[NPAIR];
__device__ float    g_importance[O_DIM];
__device__ float    g_load[O_DIM];
__device__ int      g_base[E_NUM + 1];
__device__ int      g_rows_sorted[NPAIR];
__device__ int      g_pair_of[NPAIR];
__device__ int      g_ntile;
__device__ int      g_tile_e[MAXTILE];
__device__ int      g_tile_m0[MAXTILE];
__device__ int      g_tile_done[MAXTILE];
__device__ unsigned g_obs_h[O_DIM * D_DIM / 2];
__device__ unsigned g_w1p[E_NUM * (D_DIM / 2) * H_DIM];
__device__ unsigned g_w2p[E_NUM * (H_DIM / 2) * A_DIM];
__device__ unsigned g_h[NPAIR * H_DIM / 2];
__device__ float    g_z[KSPLIT * NPAIR * A_DIM];

#define N_OBS4 (O_DIM * D_DIM / 8)
#define N_W14  (E_NUM * (D_DIM / 2) * H_DIM / 4)
#define N_W24  (E_NUM * (H_DIM / 2) * A_DIM / 4)
#define PREP_BLOCKS ((N_OBS4 + N_W14 + N_W24) / 256)   // 17920

// ---------------- helpers ----------------
__device__ __forceinline__ uint32_t smem_u32(const void* p) {
    uint32_t a;
    asm("{ .reg .u64 t; cvta.to.shared.u64 t, %1; cvt.u32.u64 %0, t; }" : "=r"(a) : "l"(p));
    return a;
}
__device__ __forceinline__ void cp_async16(uint32_t saddr, const void* gptr) {
    asm volatile("cp.async.cg.shared.global [%0], [%1], 16;" :: "r"(saddr), "l"(gptr));
}
__device__ __forceinline__ void cp_commit() {
    asm volatile("cp.async.commit_group;" ::: "memory");
}
template <int N> __device__ __forceinline__ void cp_wait() {
    asm volatile("cp.async.wait_group %0;" :: "n"(N) : "memory");
}
__device__ __forceinline__ unsigned pack_f16x2(float lo, float hi) {
    unsigned u;
    asm("cvt.rn.f16x2.f32 %0, %1, %2;" : "=r"(u) : "f"(hi), "f"(lo));
    return u;
}
__device__ __forceinline__ void ldmatrix_x4(unsigned r[4], uint32_t saddr) {
    asm volatile("ldmatrix.sync.aligned.m8n8.x4.shared.b16 {%0,%1,%2,%3}, [%4];"
                 : "=r"(r[0]), "=r"(r[1]), "=r"(r[2]), "=r"(r[3]) : "r"(saddr));
}
__device__ __forceinline__ void mma_f16(float c[4], unsigned a0, unsigned a1,
                                        unsigned a2, unsigned a3,
                                        unsigned b0, unsigned b1) {
    asm volatile(
        "mma.sync.aligned.m16n8k16.row.col.f32.f16.f16.f32 "
        "{%0,%1,%2,%3}, {%4,%5,%6,%7}, {%8,%9}, {%0,%1,%2,%3};\n"
        : "+f"(c[0]), "+f"(c[1]), "+f"(c[2]), "+f"(c[3])
        : "r"(a0), "r"(a1), "r"(a2), "r"(a3), "r"(b0), "r"(b1));
}

// ============ fused kernel 1: gate (blocks 0..1023) + prep (rest) ==========
__global__ __launch_bounds__(256) void prep_gate_kernel(const float* __restrict__ obs,
                                                        const float* __restrict__ wg,
                                                        const float* __restrict__ w1,
                                                        const float* __restrict__ w2) {
    int bid = blockIdx.x;
    int tid = threadIdx.x;

    if (bid < O_DIM) {
        int o = bid;
        const float* wrow = wg + (size_t)o * D_DIM * E_NUM;
        const float* orow = obs + (size_t)o * D_DIM;

        float acc[E_NUM];
#pragma unroll
        for (int i = 0; i < E_NUM; i++) acc[i] = 0.f;
        for (int d = tid; d < D_DIM; d += 256) {
            float x = orow[d];
            const float4* p = reinterpret_cast<const float4*>(wrow + (size_t)d * E_NUM);
            float4 v0 = p[0], v1 = p[1], v2 = p[2], v3 = p[3];
            acc[0]  += x * v0.x; acc[1]  += x * v0.y; acc[2]  += x * v0.z; acc[3]  += x * v0.w;
            acc[4]  += x * v1.x; acc[5]  += x * v1.y; acc[6]  += x * v1.z; acc[7]  += x * v1.w;
            acc[8]  += x * v2.x; acc[9]  += x * v2.y; acc[10] += x * v2.z; acc[11] += x * v2.w;
            acc[12] += x * v3.x; acc[13] += x * v3.y; acc[14] += x * v3.z; acc[15] += x * v3.w;
        }
#pragma unroll
        for (int i = 0; i < E_NUM; i++) {
#pragma unroll
            for (int off = 16; off; off >>= 1)
                acc[i] += __shfl_xor_sync(0xffffffffu, acc[i], off);
        }
        __shared__ float s[8][E_NUM];
        int warp = tid >> 5, lane = tid & 31;
        if (lane == 0) {
#pragma unroll
            for (int i = 0; i < E_NUM; i++) s[warp][i] = acc[i];
        }
        __syncthreads();
        if (tid == 0) {
            float logit[E_NUM];
            for (int e = 0; e < E_NUM; e++) {
                float t = 0.f;
                for (int w = 0; w < 8; w++) t += s[w][e];
                logit[e] = t;
            }
            bool taken[E_NUM];
            for (int e = 0; e < E_NUM; e++) taken[e] = false;
            int idx[TOPK]; float val[TOPK];
            for (int k = 0; k < TOPK; k++) {
                float best = -3.4e38f; int bi = 0;
                for (int e = 0; e < E_NUM; e++)
                    if (!taken[e] && logit[e] > best) { best = logit[e]; bi = e; }
                taken[bi] = true; idx[k] = bi; val[k] = best;
            }
            float m = val[0];
            float ex[TOPK]; float se = 0.f;
            for (int k = 0; k < TOPK; k++) { ex[k] = expf(val[k] - m); se += ex[k]; }
            float gates[E_NUM];
            for (int e = 0; e < E_NUM; e++) gates[e] = 0.f;
            for (int k = 0; k < TOPK; k++) gates[idx[k]] = ex[k] / se;
            float imp = 0.f; int ldc = 0;
            for (int e = 0; e < E_NUM; e++) { imp += gates[e]; ldc += (gates[e] > 0.f); }
            for (int k = 0; k < TOPK; k++) {
                g_topk_idx[o * TOPK + k]  = idx[k];
                g_topk_gate[o * TOPK + k] = gates[idx[k]];
            }
            g_importance[o] = imp;
            g_load[o] = (float)ldc;
        }
        return;
    }

    int idx = (bid - O_DIM) * 256 + tid;
    if (idx < N_OBS4) {
        const float4* p = reinterpret_cast<const float4*>(obs) + idx * 2;
        float4 f0 = p[0], f1 = p[1];
        uint4 u;
        u.x = pack_f16x2(f0.x, f0.y);
        u.y = pack_f16x2(f0.z, f0.w);
        u.z = pack_f16x2(f1.x, f1.y);
        u.w = pack_f16x2(f1.z, f1.w);
        reinterpret_cast<uint4*>(g_obs_h)[idx] = u;
    } else if (idx < N_OBS4 + N_W14) {
        int t = idx - N_OBS4;
        int e  = t >> 18;
        int r  = t & 262143;
        int kp = r >> 9;
        int n4 = (r & 511) * 4;
        const float* p = w1 + ((size_t)e << 21) + ((size_t)kp << 12) + n4;
        float4 f0 = __ldcs(reinterpret_cast<const float4*>(p));
        float4 f1 = __ldcs(reinterpret_cast<const float4*>(p + 2048));
        uint4 u;
        u.x = pack_f16x2(f0.x, f1.x);
        u.y = pack_f16x2(f0.y, f1.y);
        u.z = pack_f16x2(f0.z, f1.z);
        u.w = pack_f16x2(f0.w, f1.w);
        *reinterpret_cast<uint4*>(g_w1p + ((size_t)e << 20) + (kp << 11) + n4) = u;
    } else if (idx < N_OBS4 + N_W14 + N_W24) {
        int t = idx - (N_OBS4 + N_W14);
        int e  = t >> 14;
        int r  = t & 16383;
        int kp = r >> 4;
        int n4 = (r & 15) * 4;
        const float* p = w2 + ((size_t)e << 17) + (kp << 7) + n4;
        float4 f0 = __ldcs(reinterpret_cast<const float4*>(p));
        float4 f1 = __ldcs(reinterpret_cast<const float4*>(p + 64));
        uint4 u;
        u.x = pack_f16x2(f0.x, f1.x);
        u.y = pack_f16x2(f0.y, f1.y);
        u.z = pack_f16x2(f0.z, f1.z);
        u.w = pack_f16x2(f0.w, f1.w);
        *reinterpret_cast<uint4*>(g_w2p + ((size_t)e << 16) + (kp << 6) + n4) = u;
    }
}

// ---------------- K2: binning + tile table + counter reset ----------------
__global__ __launch_bounds__(512) void bin_kernel() {
    int tid = threadIdx.x;
    int warp = tid >> 5, lane = tid & 31;
    int e = warp;
    __shared__ int scnt[E_NUM];
    __shared__ int sbase[E_NUM + 1];

    if (tid < MAXTILE) g_tile_done[tid] = 0;     // reset per call (graph replay)

    int cnt = 0;
    for (int base = 0; base < O_DIM; base += 32) {
        int r = base + lane;
        bool f = (g_topk_idx[r * 4 + 0] == e) || (g_topk_idx[r * 4 + 1] == e) ||
                 (g_topk_idx[r * 4 + 2] == e) || (g_topk_idx[r * 4 + 3] == e);
        unsigned m = __ballot_sync(0xffffffffu, f);
        cnt += __popc(m);
    }
    if (lane == 0) scnt[e] = cnt;
    __syncthreads();
    if (tid == 0) {
        int s = 0;
        for (int q = 0; q < E_NUM; q++) { sbase[q] = s; s += scnt[q]; }
        sbase[E_NUM] = s;
        int t = 0;
        for (int q = 0; q < E_NUM; q++)
            for (int m0 = 0; m0 < scnt[q]; m0 += 64) {
                g_tile_e[t] = q;
                g_tile_m0[t] = m0;
                t++;
            }
        g_ntile = t;
    }
    __syncthreads();
    if (tid < E_NUM + 1) g_base[tid] = sbase[tid];

    int off = sbase[e];
    for (int base = 0; base < O_DIM; base += 32) {
        int r = base + lane;
        int j = -1;
        if      (g_topk_idx[r * 4 + 0] == e) j = 0;
        else if (g_topk_idx[r * 4 + 1] == e) j = 1;
        else if (g_topk_idx[r * 4 + 2] == e) j = 2;
        else if (g_topk_idx[r * 4 + 3] == e) j = 3;
        bool f = (j >= 0);
        unsigned m = __ballot_sync(0xffffffffu, f);
        int pos = off + __popc(m & ((1u << lane) - 1u));
        if (f) {
            g_rows_sorted[pos] = r;
            g_pair_of[r * 4 + j] = pos;
        }
        off += __popc(m);
    }
}

// ===== fused kernel 2: fc1 + action + loss + (dependent) fc2 in one grid ===
// bids [0,2304): groups of 9 = 5 fc1 + 4 action. bid 2304: loss.
// bids [2305, 2305+640): fc2 blocks — placed AFTER all producers in dispatch
// order; they spin on per-tile arrive counters (16 fc1 column-blocks each).
#define FC1_ASTAGE 5120
#define FC1_BSTAGE 8704
#define FC1_STG    (FC1_ASTAGE + FC1_BSTAGE)
#define FC1_SMEM   (3 * FC1_STG + 256)
#define FC2_ASTAGE 5120
#define FC2_BSTAGE 4608
#define FC2_STG    (FC2_ASTAGE + FC2_BSTAGE)
#define MEGA_GRID  (2305 + KSPLIT * MAXTILE)     // 2945

__device__ __forceinline__ void fc1_body(int nt, int tidx, const float* __restrict__ b1,
                                         char* smem) {
    if (tidx >= g_ntile) return;
    int e  = g_tile_e[tidx];
    int m0 = g_tile_m0[tidx];
    int pb = g_base[e];
    int ne = g_base[e + 1] - pb;

    uint32_t sb = smem_u32(smem);
    int tid = threadIdx.x;
    int lane = tid & 31, warp = tid >> 5;
    int wm = warp >> 2, wn = warp & 3;

    int* rowid = (int*)(smem + 3 * FC1_STG);
    if (tid < 64) {
        int mi = m0 + tid;
        rowid[tid] = g_rows_sorted[pb + (mi < ne ? mi : ne - 1)];
    }
    __syncthreads();

    int ar0 = tid >> 2, as0 = tid & 3;
    const char* ap0 = (const char*)g_obs_h + (size_t)rowid[ar0] * 2048 + as0 * 16;
    int bkp = tid >> 5, bns = tid & 31;
    const char* bp = (const char*)g_w1p +
                     (((size_t)e << 20) + nt * 128 + bns * 4) * 4;

    auto issue = [&](int st, int ch) {
        uint32_t s0 = sb + st * FC1_STG;
        cp_async16(s0 + ar0 * 80 + as0 * 16, ap0 + ch * 64);
        uint32_t sB = s0 + FC1_ASTAGE + bns * 16;
        cp_async16(sB + bkp * 544, bp + (size_t)(ch * 16 + bkp) * 8192);
        cp_async16(sB + (bkp + 8) * 544, bp + (size_t)(ch * 16 + bkp + 8) * 8192);
        cp_commit();
    };

    float c[2][4][4];
#pragma unroll
    for (int i = 0; i < 2; i++)
#pragma unroll
        for (int j = 0; j < 4; j++)
#pragma unroll
            for (int q = 0; q < 4; q++) c[i][j][q] = 0.f;

    issue(0, 0);
    issue(1, 1);

    uint32_t aoff = (uint32_t)(wm * 32 + (lane & 15)) * 80 + (lane >> 4) * 16;
    int colb = wn * 32 + (lane >> 2);
    int krow = lane & 3;

    for (int ch = 0; ch < 32; ch++) {
        if (ch < 31) cp_wait<1>(); else cp_wait<0>();
        __syncthreads();
        if (ch + 2 < 32) issue((ch + 2) % 3, ch + 2);

        uint32_t stg = sb + (ch % 3) * FC1_STG;
        const unsigned* Bp = (const unsigned*)(smem + (ch % 3) * FC1_STG + FC1_ASTAGE);

#pragma unroll
        for (int s = 0; s < 2; s++) {
            unsigned a[2][4];
#pragma unroll
            for (int i = 0; i < 2; i++)
                ldmatrix_x4(a[i], stg + aoff + i * 1280 + s * 32);
            unsigned b[4][2];
#pragma unroll
            for (int j = 0; j < 4; j++) {
                int w0 = (s * 8 + krow) * 136 + colb + j * 8;
                b[j][0] = Bp[w0];
                b[j][1] = Bp[w0 + 544];
            }
#pragma unroll
            for (int i = 0; i < 2; i++)
#pragma unroll
                for (int j = 0; j < 4; j++)
                    mma_f16(c[i][j], a[i][0], a[i][1], a[i][2], a[i][3], b[j][0], b[j][1]);
        }
    }

    const float* b1e = b1 + e * H_DIM + nt * 128;
#pragma unroll
    for (int i = 0; i < 2; i++) {
        int r0 = m0 + wm * 32 + i * 16 + (lane >> 2);
#pragma unroll
        for (int j = 0; j < 4; j++) {
            int cc = wn * 32 + j * 8 + 2 * (lane & 3);
            float bv0 = b1e[cc], bv1 = b1e[cc + 1];
            if (r0 < ne) {
                float y0 = fmaxf(c[i][j][0] + bv0, 0.f);
                float y1 = fmaxf(c[i][j][1] + bv1, 0.f);
                g_h[((size_t)(pb + r0) * H_DIM + nt * 128 + cc) >> 1] = pack_f16x2(y0, y1);
            }
            if (r0 + 8 < ne) {
                float y0 = fmaxf(c[i][j][2] + bv0, 0.f);
                float y1 = fmaxf(c[i][j][3] + bv1, 0.f);
                g_h[((size_t)(pb + r0 + 8) * H_DIM + nt * 128 + cc) >> 1] = pack_f16x2(y0, y1);
            }
        }
    }

    // signal: this tile column is done
    __syncthreads();
    __threadfence();
    if (tid == 0) atomicAdd(&g_tile_done[tidx], 1);
}

__device__ __forceinline__ void action_body(int o, const float* __restrict__ obs,
                                            const float* __restrict__ lastw,
                                            const float* __restrict__ lastb,
                                            float* __restrict__ out, char* smem) {
    int tid = threadIdx.x;
    float* obsS = (float*)smem;
    float* red  = obsS + D_DIM;
    float* muS  = red + 16 * A_DIM;
    float* eS   = muS + A_DIM;

    obsS[tid]       = obs[(size_t)o * D_DIM + tid];
    obsS[tid + 256] = obs[(size_t)o * D_DIM + tid + 256];
    obsS[tid + 512] = obs[(size_t)o * D_DIM + tid + 512];
    obsS[tid + 768] = obs[(size_t)o * D_DIM + tid + 768];
    __syncthreads();

    int a4 = (tid & 15) * 4;
    int chunk = tid >> 4;

    const float* lw = lastw + (size_t)o * D_DIM * A_DIM + (size_t)chunk * 64 * A_DIM + a4;
    float ax = 0.f, ay = 0.f, az = 0.f, aw = 0.f;
#pragma unroll 8
    for (int d = 0; d < 64; d++) {
        float4 w = __ldcs(reinterpret_cast<const float4*>(lw + (size_t)d * A_DIM));
        float x = obsS[chunk * 64 + d];
        ax += x * w.x; ay += x * w.y; az += x * w.z; aw += x * w.w;
    }
    red[chunk * A_DIM + a4 + 0] = ax;
    red[chunk * A_DIM + a4 + 1] = ay;
    red[chunk * A_DIM + a4 + 2] = az;
    red[chunk * A_DIM + a4 + 3] = aw;
    __syncthreads();

    if (tid < A_DIM) {
        float m = 0.f;
        for (int c = 0; c < 16; c++) m += red[c * A_DIM + tid];
        muS[tid] = m + lastb[o * A_DIM + tid];
    }
    __syncthreads();
    if (tid < A_DIM) {
        float mx = muS[0];
        for (int i = 1; i < A_DIM; i++) mx = fmaxf(mx, muS[i]);
        float t  = muS[tid] - mx;
        float ef = expf(t);
        if (ef < FLT_MIN_NORM) ef = 0.f;         // FTZ emulation
        eS[tid] = ef;
    }
    __syncthreads();
    if (tid < A_DIM) {
        float ssum = 0.f;
        for (int i = 0; i < A_DIM; i++) ssum += eS[i];
        float p = eS[tid] / ssum;
        if (p < FLT_MIN_NORM) p = 0.f;           // FTZ emulation
        out[(size_t)o * A_DIM + tid] = p;
        float lp = (p == 0.f) ? logf(1e-8f) : logf(p);
        out[(size_t)O_DIM * A_DIM + o * A_DIM + tid] = lp;
    }
}

__device__ __forceinline__ void loss_body(float* __restrict__ out, char* smem) {
    int tid = threadIdx.x;
    float* sh = (float*)smem;
    float imp[4], ld[4];
#pragma unroll
    for (int q = 0; q < 4; q++) {
        imp[q] = g_importance[tid + q * 256];
        ld[q]  = g_load[tid + q * 256];
    }
    auto reduceSum = [&](float v) -> float {
#pragma unroll
        for (int o2 = 16; o2; o2 >>= 1) v += __shfl_xor_sync(0xffffffffu, v, o2);
        if ((tid & 31) == 0) sh[tid >> 5] = v;
        __syncthreads();
        if (tid < 32) {
            float r = (tid < 8) ? sh[tid] : 0.f;
#pragma unroll
            for (int o2 = 4; o2; o2 >>= 1) r += __shfl_xor_sync(0xffffffffu, r, o2);
            if (tid == 0) sh[8] = r;
        }
        __syncthreads();
        float r = sh[8];
        __syncthreads();
        return r;
    };

    float si = reduceSum(imp[0] + imp[1] + imp[2] + imp[3]);
    float mi = si / (float)O_DIM;
    float di = 0.f;
#pragma unroll
    for (int q = 0; q < 4; q++) { float d = imp[q] - mi; di += d * d; }
    float ssi = reduceSum(di);
    float sl = reduceSum(ld[0] + ld[1] + ld[2] + ld[3]);
    float ml = sl / (float)O_DIM;
    float dl = 0.f;
#pragma unroll
    for (int q = 0; q < 4; q++) { float d = ld[q] - ml; dl += d * d; }
    float ssl = reduceSum(dl);
    if (tid == 0) {
        float vi = ssi / (float)(O_DIM - 1);
        float vl = ssl / (float)(O_DIM - 1);
        float loss = (vi / (mi * mi + 1e-10f) + vl / (ml * ml + 1e-10f)) * 0.01f;
        out[3 * O_DIM * A_DIM] = loss;
    }
}

__device__ __forceinline__ void fc2_body(int ks, int tidx, char* smem) {
    if (tidx >= g_ntile) return;
    int tid = threadIdx.x;

    // wait for all 16 fc1 column-blocks of this tile (producers have lower
    // bids, so they are dispatched before this block can hold a slot).
    if (tid == 0) {
        while (atomicAdd(&g_tile_done[tidx], 0) < 16) __nanosleep(128);
    }
    __syncthreads();
    __threadfence();

    int e  = g_tile_e[tidx];
    int m0 = g_tile_m0[tidx];
    int pb = g_base[e];
    int ne = g_base[e + 1] - pb;
    int kp0 = ks * 128;

    uint32_t sb = smem_u32(smem);
    int lane = tid & 31, warp = tid >> 5;
    int wm = warp >> 2, wn = warp & 3;

    int ar = tid >> 2, as = tid & 3;
    int rowc = pb + m0 + ar;
    if (rowc > NPAIR - 1) rowc = NPAIR - 1;
    const char* ap = (const char*)g_h + (size_t)rowc * 4096 + kp0 * 4 + as * 16;
    int bkp = tid >> 4, bns = tid & 15;
    const char* bp = (const char*)g_w2p +
                     (((size_t)e << 16) + (size_t)(kp0 + bkp) * 64 + bns * 4) * 4;

    auto issue = [&](int st, int ch) {
        uint32_t s0 = sb + st * FC2_STG;
        cp_async16(s0 + ar * 80 + as * 16, ap + ch * 64);
        cp_async16(s0 + FC2_ASTAGE + bkp * 288 + bns * 16, bp + (size_t)ch * 16 * 256);
        cp_commit();
    };

    float c[2][2][4];
#pragma unroll
    for (int i = 0; i < 2; i++)
#pragma unroll
        for (int j = 0; j < 2; j++)
#pragma unroll
            for (int q = 0; q < 4; q++) c[i][j][q] = 0.f;

    issue(0, 0);
    issue(1, 1);

    uint32_t aoff = (uint32_t)(wm * 32 + (lane & 15)) * 80 + (lane >> 4) * 16;
    int colb = wn * 16 + (lane >> 2);
    int krow = lane & 3;

    for (int ch = 0; ch < 8; ch++) {
        if (ch < 7) cp_wait<1>(); else cp_wait<0>();
        __syncthreads();
        if (ch + 2 < 8) issue((ch + 2) % 3, ch + 2);

        uint32_t stg = sb + (ch % 3) * FC2_STG;
        const unsigned* Bp = (const unsigned*)(smem + (ch % 3) * FC2_STG + FC2_ASTAGE);

#pragma unroll
        for (int s = 0; s < 2; s++) {
            unsigned a[2][4];
#pragma unroll
            for (int i = 0; i < 2; i++)
                ldmatrix_x4(a[i], stg + aoff + i * 1280 + s * 32);
            unsigned b[2][2];
#pragma unroll
            for (int j = 0; j < 2; j++) {
                int w0 = (s * 8 + krow) * 72 + colb + j * 8;
                b[j][0] = Bp[w0];
                b[j][1] = Bp[w0 + 288];
            }
#pragma unroll
            for (int i = 0; i < 2; i++)
#pragma unroll
                for (int j = 0; j < 2; j++)
                    mma_f16(c[i][j], a[i][0], a[i][1], a[i][2], a[i][3], b[j][0], b[j][1]);
        }
    }

    float* zp = g_z + (size_t)ks * NPAIR * A_DIM;
#pragma unroll
    for (int i = 0; i < 2; i++) {
        int r0 = m0 + wm * 32 + i * 16 + (lane >> 2);
#pragma unroll
        for (int j = 0; j < 2; j++) {
            int c0 = wn * 16 + j * 8 + 2 * (lane & 3);
            if (r0 < ne) {
                float* dst = zp + (size_t)(pb + r0) * A_DIM + c0;
                dst[0] = c[i][j][0];
                dst[1] = c[i][j][1];
            }
            if (r0 + 8 < ne) {
                float* dst = zp + (size_t)(pb + r0 + 8) * A_DIM + c0;
                dst[0] = c[i][j][2];
                dst[1] = c[i][j][3];
            }
        }
    }
}

__global__ __launch_bounds__(256, 3) void mega_kernel(const float* __restrict__ b1,
                                                      const float* __restrict__ obs,
                                                      const float* __restrict__ lastw,
                                                      const float* __restrict__ lastb,
                                                      float* __restrict__ out) {
    extern __shared__ char smem[];
    int bid = blockIdx.x;
    if (bid < 2304) {
        int g = bid / 9, r = bid % 9;
        if (r < 5) {
            int fid = g * 5 + r;
            fc1_body(fid & 15, fid >> 4, b1, smem);
        } else {
            action_body(g * 4 + (r - 5), obs, lastw, lastb, out, smem);
        }
        return;
    }
    if (bid == 2304) { loss_body(out, smem); return; }
    int f2 = bid - 2305;
    fc2_body(f2 & (KSPLIT - 1), f2 >> 3, smem);
}

// ---------------- combine (sums 8 k-slice partials) ----------------
__global__ __launch_bounds__(256) void combine_kernel(const float* __restrict__ b2,
                                                      float* __restrict__ out) {
    int i = blockIdx.x * blockDim.x + threadIdx.x;
    if (i >= O_DIM * A_DIM) return;
    int o = i >> 6, a = i & 63;
    float y = 0.f;
#pragma unroll
    for (int j = 0; j < TOPK; j++) {
        int eidx = g_topk_idx[o * TOPK + j];
        float g  = g_topk_gate[o * TOPK + j];
        int p    = g_pair_of[o * TOPK + j];
        size_t base = (size_t)p * A_DIM + a;
        float z = 0.f;
#pragma unroll
        for (int q = 0; q < KSPLIT; q++)
            z += g_z[base + (size_t)q * NPAIR * A_DIM];
        y += g * (z + b2[eidx * A_DIM + a]);
    }
    out[2 * O_DIM * A_DIM + i] = y;
}

// ---------------- launch ----------------------------------------------------
extern "C" void kernel_launch(void* const* d_in, const int* in_sizes, int n_in,
                              void* d_out, int out_size) {
    const float* obs   = (const float*)d_in[0];
    const float* wgate = (const float*)d_in[1];
    const float* w1    = (const float*)d_in[2];
    const float* b1    = (const float*)d_in[3];
    const float* w2    = (const float*)d_in[4];
    const float* b2    = (const float*)d_in[5];
    const float* lastw = (const float*)d_in[6];
    const float* lastb = (const float*)d_in[7];
    float* out = (float*)d_out;

    static int smem_set = 0;
    if (!smem_set) {
        cudaFuncSetAttribute(mega_kernel,
                             cudaFuncAttributeMaxDynamicSharedMemorySize, FC1_SMEM);
        smem_set = 1;
    }

    prep_gate_kernel<<<O_DIM + PREP_BLOCKS, 256>>>(obs, wgate, w1, w2);
    bin_kernel<<<1, 512>>>();
    mega_kernel<<<MEGA_GRID, 256, FC1_SMEM>>>(b1, obs, lastw, lastb, out);
    combine_kernel<<<(O_DIM * A_DIM + 255) / 256, 256>>>(b2, out);
}